// round 1
// baseline (speedup 1.0000x reference)
#include <cuda_runtime.h>

#define BB 4
#define CC 512
#define TT 2048
#define TFF 4096
#define CMIX 2048
#define NGROUPS 32

// ---------------- scratch (device globals: allocation-free) ----------------
__device__ double g_colmean[TFF];
__device__ int    g_cdf[TFF];
__device__ int    g_idx[TT];
__device__ float  g_mixed[(long)BB * CMIX * TT];  // 64 MB: [sampled | feat | fm_short]
__device__ float  g_y3[(long)BB * CC * TT];       // 16 MB: raw GEMM3 output
__device__ float  g_mu[3][BB * NGROUPS];
__device__ float  g_rstd[3][BB * NGROUPS];

// ---------------- 1) column means of frame_level_feature[0] ----------------
__global__ void colmean_kernel(const float* __restrict__ frame) {
    int t = blockIdx.x * blockDim.x + threadIdx.x;
    if (t >= TFF) return;
    const float* p = frame + t;   // batch 0
    double s = 0.0;
#pragma unroll 8
    for (int c = 0; c < CC; c++) s += (double)p[(long)c * TFF];
    g_colmean[t] = s * (1.0 / CC);
}

// ---------------- 2) normalize + cumsum + cdf (fp64, one block) ------------
__global__ void cdf_kernel() {
    __shared__ double blocksum[256];
    __shared__ double s_tot;
    int tid = threadIdx.x;
    const int CH = TFF / 256;  // 16
    double loc[CH];
    double s = 0.0;
#pragma unroll
    for (int i = 0; i < CH; i++) { s += g_colmean[tid * CH + i]; loc[i] = s; }
    blocksum[tid] = s;
    __syncthreads();
    if (tid == 0) {
        double r = 0.0;
        for (int i = 0; i < 256; i++) { double v = blocksum[i]; blocksum[i] = r; r += v; }
        s_tot = r;
    }
    __syncthreads();
    double base = blocksum[tid];
    double f = (double)TT / s_tot;
#pragma unroll
    for (int i = 0; i < CH; i++) {
        int v = (int)((base + loc[i]) * f);   // truncation == astype(int32) for positives
        if (v > TT - 1) v = TT - 1;
        g_cdf[tid * CH + i] = v;
    }
}

// ---------------- 3) idx = argmin_j |cdf[j] - i| (first occurrence) --------
__global__ void idx_kernel() {
    __shared__ int scdf[TFF];
    for (int j = threadIdx.x; j < TFF; j += blockDim.x) scdf[j] = g_cdf[j];
    __syncthreads();
    int i = blockIdx.x * blockDim.x + threadIdx.x;
    if (i >= TT) return;
    int best = 1 << 30, bj = 0;
    for (int j = 0; j < TFF; j++) {
        int d = scdf[j] - i;
        d = d < 0 ? -d : d;
        if (d < best) { best = d; bj = j; }   // strict < keeps first occurrence
    }
    g_idx[i] = bj;
}

// ---------------- 4) sampled gather into mixed channels [0,512) ------------
__global__ void gather_kernel(const float* __restrict__ frame) {
    long id = (long)blockIdx.x * blockDim.x + threadIdx.x;
    long n = (long)BB * CC * TT;
    if (id >= n) return;
    int t = (int)(id % TT);
    long bc = id / TT;
    int c = (int)(bc % CC);
    int b = (int)(bc / CC);
    g_mixed[((long)b * CMIX + c) * TT + t] =
        frame[((long)b * CC + c) * TFF + g_idx[t]];
}

// ---------------- 5) tiled SGEMM with bias:  Cb = A(MxK) * Bb(KxN) + bias ---
__global__ __launch_bounds__(256)
void sgemm_bias_kernel(const float* __restrict__ A, const float* __restrict__ Bm,
                       const float* __restrict__ bias, float* __restrict__ Cm,
                       int M, int N, int K, long strideB, long strideC, int ldc) {
    __shared__ float As[16][128];
    __shared__ float Bs[16][128];
    int tid = threadIdx.x;
    int bx = blockIdx.x, by = blockIdx.y, bz = blockIdx.z;
    const float* Bb = Bm + (long)bz * strideB;
    float* Cb = Cm + (long)bz * strideC;

    float acc[8][8];
#pragma unroll
    for (int i = 0; i < 8; i++)
#pragma unroll
        for (int j = 0; j < 8; j++) acc[i][j] = 0.f;

    int aRow = tid >> 2;            // 0..63
    int aCol = (tid & 3) * 4;       // 0..12
    int bRow = tid >> 5;            // 0..7
    int bCol = (tid & 31) * 4;      // 0..124
    int mr = (tid >> 4) * 8;
    int nc = (tid & 15) * 8;

    const float* Aptr = A + (long)(by * 128) * K;

    for (int k0 = 0; k0 < K; k0 += 16) {
#pragma unroll
        for (int r = 0; r < 2; r++) {
            int row = aRow + r * 64;
            float4 v = *reinterpret_cast<const float4*>(Aptr + (long)row * K + k0 + aCol);
            As[aCol + 0][row] = v.x; As[aCol + 1][row] = v.y;
            As[aCol + 2][row] = v.z; As[aCol + 3][row] = v.w;
        }
#pragma unroll
        for (int r = 0; r < 2; r++) {
            int row = bRow + r * 8;
            float4 v = *reinterpret_cast<const float4*>(Bb + (long)(k0 + row) * N + bx * 128 + bCol);
            *reinterpret_cast<float4*>(&Bs[row][bCol]) = v;
        }
        __syncthreads();
#pragma unroll
        for (int k = 0; k < 16; k++) {
            float a[8], b[8];
            *(float4*)(a)     = *(float4*)(&As[k][mr]);
            *(float4*)(a + 4) = *(float4*)(&As[k][mr + 4]);
            *(float4*)(b)     = *(float4*)(&Bs[k][nc]);
            *(float4*)(b + 4) = *(float4*)(&Bs[k][nc + 4]);
#pragma unroll
            for (int i = 0; i < 8; i++)
#pragma unroll
                for (int j = 0; j < 8; j++) acc[i][j] = fmaf(a[i], b[j], acc[i][j]);
        }
        __syncthreads();
    }

#pragma unroll
    for (int i = 0; i < 8; i++) {
        int m = by * 128 + mr + i;
        float bv = bias[m];
        float4 v0, v1;
        v0.x = acc[i][0] + bv; v0.y = acc[i][1] + bv; v0.z = acc[i][2] + bv; v0.w = acc[i][3] + bv;
        v1.x = acc[i][4] + bv; v1.y = acc[i][5] + bv; v1.z = acc[i][6] + bv; v1.w = acc[i][7] + bv;
        float* cp = Cb + (long)m * ldc + bx * 128 + nc;
        *reinterpret_cast<float4*>(cp)     = v0;
        *reinterpret_cast<float4*>(cp + 4) = v1;
    }
}

// ---------------- 6) GroupNorm stats (contiguous group region) -------------
__global__ void gn_stats_kernel(const float* __restrict__ buf, long bstride,
                                int chpg, int stage) {
    int g = blockIdx.x, b = blockIdx.y;
    long L = (long)chpg * TT;
    const float* p = buf + (long)b * bstride + (long)g * L;
    double s = 0.0, s2 = 0.0;
    for (long i = (long)threadIdx.x * 4; i < L; i += (long)blockDim.x * 4) {
        float4 v = *reinterpret_cast<const float4*>(p + i);
        s  += (double)v.x + (double)v.y + (double)v.z + (double)v.w;
        s2 += (double)v.x * v.x + (double)v.y * v.y + (double)v.z * v.z + (double)v.w * v.w;
    }
    __shared__ double sh[256], sh2[256];
    sh[threadIdx.x] = s; sh2[threadIdx.x] = s2;
    __syncthreads();
    for (int off = 128; off > 0; off >>= 1) {
        if (threadIdx.x < off) {
            sh[threadIdx.x]  += sh[threadIdx.x + off];
            sh2[threadIdx.x] += sh2[threadIdx.x + off];
        }
        __syncthreads();
    }
    if (threadIdx.x == 0) {
        double mean = sh[0] / (double)L;
        double var  = sh2[0] / (double)L - mean * mean;
        g_mu[stage][b * NGROUPS + g]   = (float)mean;
        g_rstd[stage][b * NGROUPS + g] = (float)rsqrt(var + 1e-5);
    }
}

// ---------------- 7) GroupNorm normalize + affine + ReLU -------------------
__global__ void gn_norm_kernel(const float* __restrict__ in, long in_bs,
                               float* __restrict__ out, long out_bs,
                               float* __restrict__ out2, long out2_bs,
                               const float* __restrict__ gamma,
                               const float* __restrict__ beta,
                               int chpg, int stage) {
    int c = blockIdx.x, b = blockIdx.y;
    int g = c / chpg;
    float mu = g_mu[stage][b * NGROUPS + g];
    float rs = g_rstd[stage][b * NGROUPS + g];
    float ga = gamma[c] * rs;
    float bt = beta[c] - mu * ga;
    const float* ip = in + (long)b * in_bs + (long)c * TT;
    float* op = out + (long)b * out_bs + (long)c * TT;
    float* op2 = out2 ? out2 + (long)b * out2_bs + (long)c * TT : (float*)0;
    for (int i = threadIdx.x * 4; i < TT; i += blockDim.x * 4) {
        float4 v = *reinterpret_cast<const float4*>(ip + i);
        v.x = fmaxf(fmaf(v.x, ga, bt), 0.f);
        v.y = fmaxf(fmaf(v.y, ga, bt), 0.f);
        v.z = fmaxf(fmaf(v.z, ga, bt), 0.f);
        v.w = fmaxf(fmaf(v.w, ga, bt), 0.f);
        *reinterpret_cast<float4*>(op + i) = v;
        if (op2) *reinterpret_cast<float4*>(op2 + i) = v;
    }
}

// ---------------- launch --------------------------------------------------
extern "C" void kernel_launch(void* const* d_in, const int* in_sizes, int n_in,
                              void* d_out, int out_size) {
    const float* feature = (const float*)d_in[0];
    const float* frame   = (const float*)d_in[1];
    const float* W1  = (const float*)d_in[2];
    const float* b1  = (const float*)d_in[3];
    const float* g1  = (const float*)d_in[4];
    const float* be1 = (const float*)d_in[5];
    const float* W2  = (const float*)d_in[6];
    const float* b2  = (const float*)d_in[7];
    const float* g2  = (const float*)d_in[8];
    const float* be2 = (const float*)d_in[9];
    const float* W3  = (const float*)d_in[10];
    const float* b3  = (const float*)d_in[11];
    const float* g3  = (const float*)d_in[12];
    const float* be3 = (const float*)d_in[13];

    float* out_mixed = (float*)d_out;                       // (4,512,2048)
    float* out_feat  = out_mixed + (long)BB * CC * TT;      // (4,1024,2048)

    float* mixed; cudaGetSymbolAddress((void**)&mixed, g_mixed);
    float* y3;    cudaGetSymbolAddress((void**)&y3, g_y3);

    // resample index path (fp64)
    colmean_kernel<<<TFF / 256, 256>>>(frame);
    cdf_kernel<<<1, 256>>>();
    idx_kernel<<<TT / 256, 256>>>();
    gather_kernel<<<(int)(((long)BB * CC * TT) / 256), 256>>>(frame);

    // GEMM2 (feat, O=1024) and GEMM1 (fm_short, O=512) into mixed buffer
    sgemm_bias_kernel<<<dim3(TT / 128, 1024 / 128, BB), 256>>>(
        W2, feature, b2, mixed + 512L * TT, 1024, TT, CC,
        (long)CC * TT, (long)CMIX * TT, TT);
    sgemm_bias_kernel<<<dim3(TT / 128, 512 / 128, BB), 256>>>(
        W1, feature, b1, mixed + 1536L * TT, 512, TT, CC,
        (long)CC * TT, (long)CMIX * TT, TT);

    // GroupNorm + ReLU (feat also streamed to output)
    gn_stats_kernel<<<dim3(NGROUPS, BB), 256>>>(mixed + 512L * TT, (long)CMIX * TT, 32, 1);
    gn_stats_kernel<<<dim3(NGROUPS, BB), 256>>>(mixed + 1536L * TT, (long)CMIX * TT, 16, 0);
    gn_norm_kernel<<<dim3(1024, BB), 256>>>(
        mixed + 512L * TT, (long)CMIX * TT,
        mixed + 512L * TT, (long)CMIX * TT,
        out_feat, (long)1024 * TT, g2, be2, 32, 1);
    gn_norm_kernel<<<dim3(512, BB), 256>>>(
        mixed + 1536L * TT, (long)CMIX * TT,
        mixed + 1536L * TT, (long)CMIX * TT,
        (float*)0, 0, g1, be1, 16, 0);

    // GEMM3 over concatenated mixed input, then GN+ReLU into output
    sgemm_bias_kernel<<<dim3(TT / 128, 512 / 128, BB), 256>>>(
        W3, mixed, b3, y3, 512, TT, CMIX,
        (long)CMIX * TT, (long)CC * TT, TT);
    gn_stats_kernel<<<dim3(NGROUPS, BB), 256>>>(y3, (long)CC * TT, 16, 2);
    gn_norm_kernel<<<dim3(512, BB), 256>>>(
        y3, (long)CC * TT,
        out_mixed, (long)CC * TT,
        (float*)0, 0, g3, be3, 16, 2);
}

// round 3
// speedup vs baseline: 1.4378x; 1.4378x over previous
#include <cuda_runtime.h>
#include <cuda_bf16.h>
#include <cstdint>

#define BB 4
#define CC 512
#define TT 2048
#define TFF 4096
#define NGROUPS 32
#define P1 512
#define P2 1024
#define M12 1536
#define K3X 1536   /* 3*512  */
#define K33 6144   /* 3*2048 */

// ---------------- scratch (device globals: allocation-free) ----------------
__device__ double g_colmean[TFF];
__device__ int    g_cdf[TFF];
__device__ int    g_idx[TT];
__device__ __nv_bfloat16 g_W12s[(size_t)M12 * K3X];
__device__ __nv_bfloat16 g_W3s[(size_t)CC * K33];
__device__ float g_bias12[M12];
__device__ __nv_bfloat16 g_bX[(size_t)BB * TT * K3X];   // 25 MB
__device__ __nv_bfloat16 g_b3[(size_t)BB * TT * K33];   // 100 MB
__device__ float g_y12[(size_t)BB * M12 * TT];          // 50 MB
__device__ float g_y3[(size_t)BB * CC * TT];            // 16 MB
__device__ float g_mu[3][BB * NGROUPS];
__device__ float g_rstd[3][BB * NGROUPS];

// ---------------- PTX helpers ----------------------------------------------
__device__ __forceinline__ uint32_t smem_u32(const void* p) {
    uint32_t a;
    asm("{ .reg .u64 t; cvta.to.shared.u64 t, %1; cvt.u32.u64 %0, t; }"
        : "=r"(a) : "l"(p));
    return a;
}
__device__ __forceinline__ void ldsm4(uint32_t* r, uint32_t addr) {
    asm volatile("ldmatrix.sync.aligned.m8n8.x4.shared.b16 {%0,%1,%2,%3}, [%4];"
                 : "=r"(r[0]), "=r"(r[1]), "=r"(r[2]), "=r"(r[3]) : "r"(addr));
}
__device__ __forceinline__ void ldsm2(uint32_t* r, uint32_t addr) {
    asm volatile("ldmatrix.sync.aligned.m8n8.x2.shared.b16 {%0,%1}, [%2];"
                 : "=r"(r[0]), "=r"(r[1]) : "r"(addr));
}
__device__ __forceinline__ void mma16816(float* c, const uint32_t* a, const uint32_t* b) {
    asm volatile("mma.sync.aligned.m16n8k16.row.col.f32.bf16.bf16.f32 "
                 "{%0,%1,%2,%3}, {%4,%5,%6,%7}, {%8,%9}, {%0,%1,%2,%3};"
                 : "+f"(c[0]), "+f"(c[1]), "+f"(c[2]), "+f"(c[3])
                 : "r"(a[0]), "r"(a[1]), "r"(a[2]), "r"(a[3]),
                   "r"(b[0]), "r"(b[1]));
}

// ---------------- 1) column means of frame_level_feature[0] ----------------
__global__ void colmean_kernel(const float* __restrict__ frame) {
    int t = blockIdx.x * blockDim.x + threadIdx.x;
    if (t >= TFF) return;
    const float* p = frame + t;
    double s = 0.0;
#pragma unroll 8
    for (int c = 0; c < CC; c++) s += (double)p[(long)c * TFF];
    g_colmean[t] = s * (1.0 / CC);
}

// ---------------- 2) normalize + cumsum + cdf (fp64, one block) ------------
__global__ void cdf_kernel() {
    __shared__ double blocksum[256];
    __shared__ double s_tot;
    int tid = threadIdx.x;
    const int CH = TFF / 256;
    double loc[CH];
    double s = 0.0;
#pragma unroll
    for (int i = 0; i < CH; i++) { s += g_colmean[tid * CH + i]; loc[i] = s; }
    blocksum[tid] = s;
    __syncthreads();
    if (tid == 0) {
        double r = 0.0;
        for (int i = 0; i < 256; i++) { double v = blocksum[i]; blocksum[i] = r; r += v; }
        s_tot = r;
    }
    __syncthreads();
    double base = blocksum[tid];
    double f = (double)TT / s_tot;
#pragma unroll
    for (int i = 0; i < CH; i++) {
        int v = (int)((base + loc[i]) * f);
        if (v > TT - 1) v = TT - 1;
        g_cdf[tid * CH + i] = v;
    }
}

// ---------------- 3) idx = argmin_j |cdf[j] - i| ----------------------------
__global__ void idx_kernel() {
    __shared__ int scdf[TFF];
    for (int j = threadIdx.x; j < TFF; j += blockDim.x) scdf[j] = g_cdf[j];
    __syncthreads();
    int i = blockIdx.x * blockDim.x + threadIdx.x;
    if (i >= TT) return;
    int best = 1 << 30, bj = 0;
    for (int j = 0; j < TFF; j++) {
        int d = scdf[j] - i;
        d = d < 0 ? -d : d;
        if (d < best) { best = d; bj = j; }
    }
    g_idx[i] = bj;
}

// ---------------- 4) weight split: A' = [hi | hi | lo] ----------------------
__global__ void splitw_kernel(const float* __restrict__ W, __nv_bfloat16* __restrict__ A,
                              int M, int K) {
    int i = blockIdx.x * blockDim.x + threadIdx.x;
    if (i >= M * K) return;
    int m = i / K, k = i % K;
    float w = W[i];
    __nv_bfloat16 hi = __float2bfloat16(w);
    __nv_bfloat16 lo = __float2bfloat16(w - __bfloat162float(hi));
    size_t base = (size_t)m * 3 * K;
    A[base + k] = hi; A[base + K + k] = hi; A[base + 2 * K + k] = lo;
}

__global__ void bias12_kernel(const float* __restrict__ b2, const float* __restrict__ b1) {
    int i = blockIdx.x * blockDim.x + threadIdx.x;
    if (i < P2) g_bias12[i] = b2[i];
    else if (i < M12) g_bias12[i] = b1[i - P2];
}

// ---------------- 5) feature transpose-split: B' = [hi ; lo ; hi] -----------
__global__ void splitx_kernel(const float* __restrict__ X) {
    __shared__ float tile[32][33];
    int b = blockIdx.z, c0 = blockIdx.y * 32, t0 = blockIdx.x * 32;
    int tx = threadIdx.x, ty = threadIdx.y;
    tile[ty][tx] = X[((long)b * CC + c0 + ty) * TT + t0 + tx];
    __syncthreads();
    float w = tile[tx][ty];
    int n = t0 + ty, k = c0 + tx;
    __nv_bfloat16 hi = __float2bfloat16(w);
    __nv_bfloat16 lo = __float2bfloat16(w - __bfloat162float(hi));
    __nv_bfloat16* d = g_bX + ((size_t)b * TT + n) * K3X;
    d[k] = hi; d[512 + k] = lo; d[1024 + k] = hi;
}

// ---------------- 6) gather + transpose-split into g_b3[.., 0:512] ----------
__global__ void gather_split_kernel(const float* __restrict__ frame) {
    __shared__ float tile[32][33];
    int b = blockIdx.z, c0 = blockIdx.y * 32, t0 = blockIdx.x * 32;
    int tx = threadIdx.x, ty = threadIdx.y;
    tile[ty][tx] = frame[((long)b * CC + c0 + ty) * TFF + g_idx[t0 + tx]];
    __syncthreads();
    float w = tile[tx][ty];
    int n = t0 + ty, k = c0 + tx;
    __nv_bfloat16 hi = __float2bfloat16(w);
    __nv_bfloat16 lo = __float2bfloat16(w - __bfloat162float(hi));
    __nv_bfloat16* d = g_b3 + ((size_t)b * TT + n) * K33;
    d[k] = hi; d[2048 + k] = lo; d[4096 + k] = hi;
}

// ---------------- 7) GroupNorm stats ----------------------------------------
__global__ void gn_stats_kernel(const float* __restrict__ buf, long bstride,
                                int chpg, int stage) {
    int g = blockIdx.x, b = blockIdx.y;
    long L = (long)chpg * TT;
    const float* p = buf + (long)b * bstride + (long)g * L;
    double s = 0.0, s2 = 0.0;
    for (long i = (long)threadIdx.x * 4; i < L; i += (long)blockDim.x * 4) {
        float4 v = *reinterpret_cast<const float4*>(p + i);
        s  += (double)v.x + (double)v.y + (double)v.z + (double)v.w;
        s2 += (double)v.x * v.x + (double)v.y * v.y + (double)v.z * v.z + (double)v.w * v.w;
    }
    __shared__ double sh[256], sh2[256];
    sh[threadIdx.x] = s; sh2[threadIdx.x] = s2;
    __syncthreads();
    for (int off = 128; off > 0; off >>= 1) {
        if (threadIdx.x < off) {
            sh[threadIdx.x]  += sh[threadIdx.x + off];
            sh2[threadIdx.x] += sh2[threadIdx.x + off];
        }
        __syncthreads();
    }
    if (threadIdx.x == 0) {
        double mean = sh[0] / (double)L;
        double var  = sh2[0] / (double)L - mean * mean;
        g_mu[stage][b * NGROUPS + g]   = (float)mean;
        g_rstd[stage][b * NGROUPS + g] = (float)rsqrt(var + 1e-5);
    }
}

// ------- 8) GN+ReLU, write optional fp32 out AND transposed bf16 split ------
__global__ void gn_split_kernel(const float* __restrict__ y, long ybs,
                                int chpg, int stage, int chanoff,
                                const float* __restrict__ gamma,
                                const float* __restrict__ beta,
                                float* __restrict__ outf, long obs) {
    __shared__ float tile[32][33];
    int b = blockIdx.z, c0 = blockIdx.y * 32, t0 = blockIdx.x * 32;
    int tx = threadIdx.x, ty = threadIdx.y;
    int c = c0 + ty;
    float mu = g_mu[stage][b * NGROUPS + c / chpg];
    float rs = g_rstd[stage][b * NGROUPS + c / chpg];
    float ga = gamma[c] * rs, bt = beta[c] - mu * ga;
    float v = fmaxf(fmaf(y[(long)b * ybs + (long)c * TT + t0 + tx], ga, bt), 0.f);
    if (outf) outf[(long)b * obs + (long)c * TT + t0 + tx] = v;
    tile[ty][tx] = v;
    __syncthreads();
    float w = tile[tx][ty];
    int n = t0 + ty, k = chanoff + c0 + tx;
    __nv_bfloat16 hi = __float2bfloat16(w);
    __nv_bfloat16 lo = __float2bfloat16(w - __bfloat162float(hi));
    __nv_bfloat16* d = g_b3 + ((size_t)b * TT + n) * K33;
    d[k] = hi; d[2048 + k] = lo; d[4096 + k] = hi;
}

// ---------------- 9) final GN+ReLU (fp32 out only) ---------------------------
__global__ void gn_out_kernel(const float* __restrict__ in, long in_bs,
                              float* __restrict__ out, long out_bs,
                              const float* __restrict__ gamma,
                              const float* __restrict__ beta,
                              int chpg, int stage) {
    int c = blockIdx.x, b = blockIdx.y;
    int g = c / chpg;
    float mu = g_mu[stage][b * NGROUPS + g];
    float rs = g_rstd[stage][b * NGROUPS + g];
    float ga = gamma[c] * rs, bt = beta[c] - mu * ga;
    const float* ip = in + (long)b * in_bs + (long)c * TT;
    float* op = out + (long)b * out_bs + (long)c * TT;
    for (int i = threadIdx.x * 4; i < TT; i += blockDim.x * 4) {
        float4 v = *reinterpret_cast<const float4*>(ip + i);
        v.x = fmaxf(fmaf(v.x, ga, bt), 0.f);
        v.y = fmaxf(fmaf(v.y, ga, bt), 0.f);
        v.z = fmaxf(fmaf(v.z, ga, bt), 0.f);
        v.w = fmaxf(fmaf(v.w, ga, bt), 0.f);
        *reinterpret_cast<float4*>(op + i) = v;
    }
}

// ---------------- 10) HMMA bf16 GEMM: C = A' x B'^T + bias -------------------
// A' [M, K3] row-major, B' [B][N=2048, K3] row-major (both K-contiguous).
// C [B][M, 2048] fp32. Block tile 128x128, BK=32, 8 warps of 64x32.
#define SPITCH 40   /* bf16 elems per smem row (80 B) */

__global__ __launch_bounds__(256)
void wmma_gemm_kernel(const __nv_bfloat16* __restrict__ A,
                      const __nv_bfloat16* __restrict__ Bm,
                      const float* __restrict__ bias,
                      float* __restrict__ Cm,
                      int K3, long bsB, long bsC) {
    __shared__ __nv_bfloat16 As[2][128 * SPITCH];
    __shared__ __nv_bfloat16 Bs[2][128 * SPITCH];
    int tid = threadIdx.x, lane = tid & 31, wid = tid >> 5;
    int bx = blockIdx.x, by = blockIdx.y, bz = blockIdx.z;
    int wm = (wid & 1) * 64, wn = (wid >> 1) * 32;

    const __nv_bfloat16* Ab = A + (long)(by * 128) * K3;
    const __nv_bfloat16* Bb = Bm + (long)bz * bsB + (long)(bx * 128) * K3;

    int grow = tid >> 2, gq = tid & 3;
    const __nv_bfloat16* ga0 = Ab + (long)grow * K3 + gq * 8;
    const __nv_bfloat16* ga1 = Ab + (long)(grow + 64) * K3 + gq * 8;
    const __nv_bfloat16* gb0 = Bb + (long)grow * K3 + gq * 8;
    const __nv_bfloat16* gb1 = Bb + (long)(grow + 64) * K3 + gq * 8;
    int soff = grow * SPITCH + gq * 8;

    uint32_t as_base = smem_u32(&As[0][0]);
    uint32_t bs_base = smem_u32(&Bs[0][0]);
    const uint32_t STG = 128 * SPITCH * 2;

    uint32_t a_lane = ((lane & 15) * SPITCH + (lane >> 4) * 8) * 2;
    uint32_t b_lane = ((lane & 7) * SPITCH + ((lane >> 3) & 1) * 8) * 2;

    float acc[4][4][4];
#pragma unroll
    for (int i = 0; i < 4; i++)
#pragma unroll
        for (int j = 0; j < 4; j++)
#pragma unroll
            for (int r = 0; r < 4; r++) acc[i][j][r] = 0.f;

    uint4 pa0 = *(const uint4*)ga0, pa1 = *(const uint4*)ga1;
    uint4 pb0 = *(const uint4*)gb0, pb1 = *(const uint4*)gb1;
    *(uint4*)&As[0][soff] = pa0; *(uint4*)&As[0][soff + 64 * SPITCH] = pa1;
    *(uint4*)&Bs[0][soff] = pb0; *(uint4*)&Bs[0][soff + 64 * SPITCH] = pb1;
    __syncthreads();

    int NT = K3 >> 5;
    for (int t = 0; t < NT; t++) {
        int cur = t & 1;
        if (t + 1 < NT) {
            long k0 = (long)(t + 1) * 32;
            pa0 = *(const uint4*)(ga0 + k0); pa1 = *(const uint4*)(ga1 + k0);
            pb0 = *(const uint4*)(gb0 + k0); pb1 = *(const uint4*)(gb1 + k0);
        }
        uint32_t abase = as_base + cur * STG + a_lane + wm * (SPITCH * 2);
        uint32_t bbase = bs_base + cur * STG + b_lane + wn * (SPITCH * 2);
#pragma unroll
        for (int ks = 0; ks < 2; ks++) {
            uint32_t a[4][4], b[4][2];
#pragma unroll
            for (int fm = 0; fm < 4; fm++)
                ldsm4(a[fm], abase + fm * 16 * (SPITCH * 2) + ks * 32);
#pragma unroll
            for (int fn = 0; fn < 4; fn++)
                ldsm2(b[fn], bbase + fn * 8 * (SPITCH * 2) + ks * 32);
#pragma unroll
            for (int fm = 0; fm < 4; fm++)
#pragma unroll
                for (int fn = 0; fn < 4; fn++)
                    mma16816(acc[fm][fn], a[fm], b[fn]);
        }
        if (t + 1 < NT) {
            int nxt = cur ^ 1;
            *(uint4*)&As[nxt][soff] = pa0; *(uint4*)&As[nxt][soff + 64 * SPITCH] = pa1;
            *(uint4*)&Bs[nxt][soff] = pb0; *(uint4*)&Bs[nxt][soff + 64 * SPITCH] = pb1;
            __syncthreads();
        }
    }

    int rowg = lane >> 2, colg = (lane & 3) * 2;
    float* Cb = Cm + (long)bz * bsC;
#pragma unroll
    for (int fm = 0; fm < 4; fm++) {
        int m0 = by * 128 + wm + fm * 16 + rowg;
        float bv0 = bias[m0], bv1 = bias[m0 + 8];
#pragma unroll
        for (int fn = 0; fn < 4; fn++) {
            int n0 = bx * 128 + wn + fn * 8 + colg;
            float2 v0 = { acc[fm][fn][0] + bv0, acc[fm][fn][1] + bv0 };
            float2 v1 = { acc[fm][fn][2] + bv1, acc[fm][fn][3] + bv1 };
            *reinterpret_cast<float2*>(Cb + (long)m0 * TT + n0) = v0;
            *reinterpret_cast<float2*>(Cb + (long)(m0 + 8) * TT + n0) = v1;
        }
    }
}

// ---------------- launch -----------------------------------------------------
extern "C" void kernel_launch(void* const* d_in, const int* in_sizes, int n_in,
                              void* d_out, int out_size) {
    const float* feature = (const float*)d_in[0];
    const float* frame   = (const float*)d_in[1];
    const float* W1  = (const float*)d_in[2];
    const float* b1  = (const float*)d_in[3];
    const float* g1  = (const float*)d_in[4];
    const float* be1 = (const float*)d_in[5];
    const float* W2  = (const float*)d_in[6];
    const float* b2  = (const float*)d_in[7];
    const float* g2  = (const float*)d_in[8];
    const float* be2 = (const float*)d_in[9];
    const float* W3  = (const float*)d_in[10];
    const float* b3  = (const float*)d_in[11];
    const float* g3  = (const float*)d_in[12];
    const float* be3 = (const float*)d_in[13];

    float* out_mixed = (float*)d_out;
    float* out_feat  = out_mixed + (long)BB * CC * TT;

    __nv_bfloat16 *w12s, *w3s, *bX, *b3buf;
    float *y12, *y3, *bias12;
    cudaGetSymbolAddress((void**)&w12s, g_W12s);
    cudaGetSymbolAddress((void**)&w3s, g_W3s);
    cudaGetSymbolAddress((void**)&bX,  g_bX);
    cudaGetSymbolAddress((void**)&b3buf, g_b3);
    cudaGetSymbolAddress((void**)&y12, g_y12);
    cudaGetSymbolAddress((void**)&y3, g_y3);
    cudaGetSymbolAddress((void**)&bias12, g_bias12);

    // weight splits (W2 stacked above W1) + bias concat
    splitw_kernel<<<(P2 * CC) / 256, 256>>>(W2, w12s, P2, CC);
    splitw_kernel<<<(P1 * CC) / 256, 256>>>(W1, w12s + (size_t)P2 * K3X, P1, CC);
    splitw_kernel<<<(CC * 2048) / 256, 256>>>(W3, w3s, CC, 2048);
    bias12_kernel<<<M12 / 256, 256>>>(b2, b1);

    // feature transpose-split
    splitx_kernel<<<dim3(TT / 32, CC / 32, BB), dim3(32, 32)>>>(feature);

    // resample index path (fp64)
    colmean_kernel<<<TFF / 256, 256>>>(frame);
    cdf_kernel<<<1, 256>>>();
    idx_kernel<<<TT / 256, 256>>>();
    gather_split_kernel<<<dim3(TT / 32, CC / 32, BB), dim3(32, 32)>>>(frame);

    // stacked GEMM1+2: y12[B][1536][TT]
    wmma_gemm_kernel<<<dim3(TT / 128, M12 / 128, BB), 256>>>(
        w12s, bX, bias12, y12, K3X, (long)TT * K3X, (long)M12 * TT);

    // GroupNorm + ReLU; feat -> fp32 out + bf16 split; fm_short -> bf16 split
    gn_stats_kernel<<<dim3(NGROUPS, BB), 256>>>(y12, (long)M12 * TT, P2 / NGROUPS, 1);
    gn_stats_kernel<<<dim3(NGROUPS, BB), 256>>>(y12 + (long)P2 * TT, (long)M12 * TT,
                                                P1 / NGROUPS, 0);
    gn_split_kernel<<<dim3(TT / 32, P2 / 32, BB), dim3(32, 32)>>>(
        y12, (long)M12 * TT, P2 / NGROUPS, 1, 512, g2, be2, out_feat, (long)P2 * TT);
    gn_split_kernel<<<dim3(TT / 32, P1 / 32, BB), dim3(32, 32)>>>(
        y12 + (long)P2 * TT, (long)M12 * TT, P1 / NGROUPS, 0, 1536, g1, be1,
        (float*)0, 0);

    // GEMM3 over concatenated (split) input, then final GN+ReLU
    wmma_gemm_kernel<<<dim3(TT / 128, CC / 128, BB), 256>>>(
        w3s, b3buf, b3, y3, K33, (long)TT * K33, (long)CC * TT);
    gn_stats_kernel<<<dim3(NGROUPS, BB), 256>>>(y3, (long)CC * TT, CC / NGROUPS, 2);
    gn_out_kernel<<<dim3(CC, BB), 256>>>(
        y3, (long)CC * TT, out_mixed, (long)CC * TT, g3, be3, CC / NGROUPS, 2);
}

// round 4
// speedup vs baseline: 1.5061x; 1.0475x over previous
#include <cuda_runtime.h>
#include <cuda_bf16.h>
#include <cstdint>

#define BB 4
#define CC 512
#define TT 2048
#define TFF 4096
#define NGROUPS 32
#define P1 512
#define P2 1024
#define M12 1536
#define K3X 1536   /* 3*512  */
#define K33 6144   /* 3*2048 */

// ---------------- scratch (device globals: allocation-free) ----------------
__device__ double g_colmean[TFF];
__device__ int    g_cdf[TFF];
__device__ int    g_idx[TT];
__device__ __nv_bfloat16 g_W12s[(size_t)M12 * K3X];
__device__ __nv_bfloat16 g_W3s[(size_t)CC * K33];
__device__ float g_bias12[M12];
__device__ __nv_bfloat16 g_bX[(size_t)BB * TT * K3X];   // 25 MB
__device__ __nv_bfloat16 g_b3[(size_t)BB * TT * K33];   // 100 MB
__device__ float g_y12[(size_t)BB * M12 * TT];          // 50 MB
__device__ float g_y3[(size_t)BB * CC * TT];            // 16 MB
__device__ float g_mu[3][BB * NGROUPS];
__device__ float g_rstd[3][BB * NGROUPS];

// ---------------- PTX helpers ----------------------------------------------
__device__ __forceinline__ uint32_t smem_u32(const void* p) {
    uint32_t a;
    asm("{ .reg .u64 t; cvta.to.shared.u64 t, %1; cvt.u32.u64 %0, t; }"
        : "=r"(a) : "l"(p));
    return a;
}
__device__ __forceinline__ void ldsm4(uint32_t* r, uint32_t addr) {
    asm volatile("ldmatrix.sync.aligned.m8n8.x4.shared.b16 {%0,%1,%2,%3}, [%4];"
                 : "=r"(r[0]), "=r"(r[1]), "=r"(r[2]), "=r"(r[3]) : "r"(addr));
}
__device__ __forceinline__ void mma16816(float* c, const uint32_t* a, const uint32_t* b) {
    asm volatile("mma.sync.aligned.m16n8k16.row.col.f32.bf16.bf16.f32 "
                 "{%0,%1,%2,%3}, {%4,%5,%6,%7}, {%8,%9}, {%0,%1,%2,%3};"
                 : "+f"(c[0]), "+f"(c[1]), "+f"(c[2]), "+f"(c[3])
                 : "r"(a[0]), "r"(a[1]), "r"(a[2]), "r"(a[3]),
                   "r"(b[0]), "r"(b[1]));
}
__device__ __forceinline__ void cp16(uint32_t dst, const void* src) {
    asm volatile("cp.async.cg.shared.global [%0], [%1], 16;" :: "r"(dst), "l"(src));
}
#define CP_COMMIT() asm volatile("cp.async.commit_group;")
#define CP_WAIT1()  asm volatile("cp.async.wait_group 1;")

// ---------------- 0) prep: split W2,W1 + concat bias -------------------------
__global__ void prep_kernel(const float* __restrict__ W2, const float* __restrict__ W1,
                            const float* __restrict__ b2, const float* __restrict__ b1) {
    int bid = blockIdx.x;
    if (bid < 2048) {                       // W2: P2 x CC
        int i = bid * 256 + threadIdx.x;
        int m = i / CC, k = i % CC;
        float w = W2[i];
        __nv_bfloat16 hi = __float2bfloat16(w);
        __nv_bfloat16 lo = __float2bfloat16(w - __bfloat162float(hi));
        size_t base = (size_t)m * K3X;
        g_W12s[base + k] = hi; g_W12s[base + CC + k] = hi; g_W12s[base + 2 * CC + k] = lo;
    } else if (bid < 3072) {                // W1: P1 x CC
        int i = (bid - 2048) * 256 + threadIdx.x;
        int m = i / CC, k = i % CC;
        float w = W1[i];
        __nv_bfloat16 hi = __float2bfloat16(w);
        __nv_bfloat16 lo = __float2bfloat16(w - __bfloat162float(hi));
        size_t base = (size_t)(P2 + m) * K3X;
        g_W12s[base + k] = hi; g_W12s[base + CC + k] = hi; g_W12s[base + 2 * CC + k] = lo;
    } else {                                // bias concat
        int i = (bid - 3072) * 256 + threadIdx.x;
        if (i < P2) g_bias12[i] = b2[i];
        else if (i < M12) g_bias12[i] = b1[i - P2];
    }
}

// ---------------- weight split for W3 ----------------------------------------
__global__ void splitw_kernel(const float* __restrict__ W, __nv_bfloat16* __restrict__ A,
                              int M, int K) {
    int i = blockIdx.x * blockDim.x + threadIdx.x;
    if (i >= M * K) return;
    int m = i / K, k = i % K;
    float w = W[i];
    __nv_bfloat16 hi = __float2bfloat16(w);
    __nv_bfloat16 lo = __float2bfloat16(w - __bfloat162float(hi));
    size_t base = (size_t)m * 3 * K;
    A[base + k] = hi; A[base + K + k] = hi; A[base + 2 * K + k] = lo;
}

// ---------------- 1) column means of frame_level_feature[0] ----------------
__global__ void colmean_kernel(const float* __restrict__ frame) {
    int t = blockIdx.x * blockDim.x + threadIdx.x;
    if (t >= TFF) return;
    const float* p = frame + t;
    double s = 0.0;
#pragma unroll 8
    for (int c = 0; c < CC; c++) s += (double)p[(long)c * TFF];
    g_colmean[t] = s * (1.0 / CC);
}

// ---------------- 2) normalize + cumsum + cdf (fp64, one block) ------------
__global__ void cdf_kernel() {
    __shared__ double blocksum[256];
    __shared__ double s_tot;
    int tid = threadIdx.x;
    const int CH = TFF / 256;
    double loc[CH];
    double s = 0.0;
#pragma unroll
    for (int i = 0; i < CH; i++) { s += g_colmean[tid * CH + i]; loc[i] = s; }
    blocksum[tid] = s;
    __syncthreads();
    if (tid == 0) {
        double r = 0.0;
        for (int i = 0; i < 256; i++) { double v = blocksum[i]; blocksum[i] = r; r += v; }
        s_tot = r;
    }
    __syncthreads();
    double base = blocksum[tid];
    double f = (double)TT / s_tot;
#pragma unroll
    for (int i = 0; i < CH; i++) {
        int v = (int)((base + loc[i]) * f);
        if (v > TT - 1) v = TT - 1;
        g_cdf[tid * CH + i] = v;
    }
}

// ---------------- 3) idx = argmin_j |cdf[j] - i| ----------------------------
__global__ void idx_kernel() {
    __shared__ int scdf[TFF];
    for (int j = threadIdx.x; j < TFF; j += blockDim.x) scdf[j] = g_cdf[j];
    __syncthreads();
    int i = blockIdx.x * blockDim.x + threadIdx.x;
    if (i >= TT) return;
    int best = 1 << 30, bj = 0;
    for (int j = 0; j < TFF; j++) {
        int d = scdf[j] - i;
        d = d < 0 ? -d : d;
        if (d < best) { best = d; bj = j; }
    }
    g_idx[i] = bj;
}

// ---------------- 5) feature transpose-split: B' = [hi ; lo ; hi] -----------
__global__ void splitx_kernel(const float* __restrict__ X) {
    __shared__ float tile[32][33];
    int b = blockIdx.z, c0 = blockIdx.y * 32, t0 = blockIdx.x * 32;
    int tx = threadIdx.x, ty = threadIdx.y;
    tile[ty][tx] = X[((long)b * CC + c0 + ty) * TT + t0 + tx];
    __syncthreads();
    float w = tile[tx][ty];
    int n = t0 + ty, k = c0 + tx;
    __nv_bfloat16 hi = __float2bfloat16(w);
    __nv_bfloat16 lo = __float2bfloat16(w - __bfloat162float(hi));
    __nv_bfloat16* d = g_bX + ((size_t)b * TT + n) * K3X;
    d[k] = hi; d[512 + k] = lo; d[1024 + k] = hi;
}

// ---------------- 6) gather + transpose-split into g_b3[.., 0:512] ----------
__global__ void gather_split_kernel(const float* __restrict__ frame) {
    __shared__ float tile[32][33];
    int b = blockIdx.z, c0 = blockIdx.y * 32, t0 = blockIdx.x * 32;
    int tx = threadIdx.x, ty = threadIdx.y;
    tile[ty][tx] = frame[((long)b * CC + c0 + ty) * TFF + g_idx[t0 + tx]];
    __syncthreads();
    float w = tile[tx][ty];
    int n = t0 + ty, k = c0 + tx;
    __nv_bfloat16 hi = __float2bfloat16(w);
    __nv_bfloat16 lo = __float2bfloat16(w - __bfloat162float(hi));
    __nv_bfloat16* d = g_b3 + ((size_t)b * TT + n) * K33;
    d[k] = hi; d[2048 + k] = lo; d[4096 + k] = hi;
}

// ---------------- 7) GroupNorm stats ----------------------------------------
__global__ void gn_stats_kernel(const float* __restrict__ buf, long bstride,
                                int chpg, int stage) {
    int g = blockIdx.x, b = blockIdx.y;
    long L = (long)chpg * TT;
    const float* p = buf + (long)b * bstride + (long)g * L;
    double s = 0.0, s2 = 0.0;
    for (long i = (long)threadIdx.x * 4; i < L; i += (long)blockDim.x * 4) {
        float4 v = *reinterpret_cast<const float4*>(p + i);
        s  += (double)v.x + (double)v.y + (double)v.z + (double)v.w;
        s2 += (double)v.x * v.x + (double)v.y * v.y + (double)v.z * v.z + (double)v.w * v.w;
    }
    __shared__ double sh[256], sh2[256];
    sh[threadIdx.x] = s; sh2[threadIdx.x] = s2;
    __syncthreads();
    for (int off = 128; off > 0; off >>= 1) {
        if (threadIdx.x < off) {
            sh[threadIdx.x]  += sh[threadIdx.x + off];
            sh2[threadIdx.x] += sh2[threadIdx.x + off];
        }
        __syncthreads();
    }
    if (threadIdx.x == 0) {
        double mean = sh[0] / (double)L;
        double var  = sh2[0] / (double)L - mean * mean;
        g_mu[stage][b * NGROUPS + g]   = (float)mean;
        g_rstd[stage][b * NGROUPS + g] = (float)rsqrt(var + 1e-5);
    }
}

// ------- 8) GN+ReLU, write optional fp32 out AND transposed bf16 split ------
__global__ void gn_split_kernel(const float* __restrict__ y, long ybs,
                                int chpg, int stage, int chanoff,
                                const float* __restrict__ gamma,
                                const float* __restrict__ beta,
                                float* __restrict__ outf, long obs) {
    __shared__ float tile[32][33];
    int b = blockIdx.z, c0 = blockIdx.y * 32, t0 = blockIdx.x * 32;
    int tx = threadIdx.x, ty = threadIdx.y;
    int c = c0 + ty;
    float mu = g_mu[stage][b * NGROUPS + c / chpg];
    float rs = g_rstd[stage][b * NGROUPS + c / chpg];
    float ga = gamma[c] * rs, bt = beta[c] - mu * ga;
    float v = fmaxf(fmaf(y[(long)b * ybs + (long)c * TT + t0 + tx], ga, bt), 0.f);
    if (outf) outf[(long)b * obs + (long)c * TT + t0 + tx] = v;
    tile[ty][tx] = v;
    __syncthreads();
    float w = tile[tx][ty];
    int n = t0 + ty, k = chanoff + c0 + tx;
    __nv_bfloat16 hi = __float2bfloat16(w);
    __nv_bfloat16 lo = __float2bfloat16(w - __bfloat162float(hi));
    __nv_bfloat16* d = g_b3 + ((size_t)b * TT + n) * K33;
    d[k] = hi; d[2048 + k] = lo; d[4096 + k] = hi;
}

// ---------------- 9) final GN+ReLU (fp32 out only) ---------------------------
__global__ void gn_out_kernel(const float* __restrict__ in, long in_bs,
                              float* __restrict__ out, long out_bs,
                              const float* __restrict__ gamma,
                              const float* __restrict__ beta,
                              int chpg, int stage) {
    int c = blockIdx.x, b = blockIdx.y;
    int g = c / chpg;
    float mu = g_mu[stage][b * NGROUPS + g];
    float rs = g_rstd[stage][b * NGROUPS + g];
    float ga = gamma[c] * rs, bt = beta[c] - mu * ga;
    const float* ip = in + (long)b * in_bs + (long)c * TT;
    float* op = out + (long)b * out_bs + (long)c * TT;
    for (int i = threadIdx.x * 4; i < TT; i += blockDim.x * 4) {
        float4 v = *reinterpret_cast<const float4*>(ip + i);
        v.x = fmaxf(fmaf(v.x, ga, bt), 0.f);
        v.y = fmaxf(fmaf(v.y, ga, bt), 0.f);
        v.z = fmaxf(fmaf(v.z, ga, bt), 0.f);
        v.w = fmaxf(fmaf(v.w, ga, bt), 0.f);
        *reinterpret_cast<float4*>(op + i) = v;
    }
}

// ---------------- 10) HMMA bf16 GEMM, cp.async 3-stage pipeline --------------
// A' [M, K3] row-major, B' [B][N=2048, K3] row-major (both K-contiguous).
// C [B][M, 2048] fp32. Block tile 128x128, BK=32, 8 warps of 64x32.
#define SPITCH 40                 /* bf16 elems per smem row (80 B) */
#define STG_BYTES (128 * SPITCH * 2)      /* 10240 per matrix */
#define STAGE_BYTES (2 * STG_BYTES)       /* 20480 per stage */

__global__ __launch_bounds__(256, 2)
void wmma_gemm_kernel(const __nv_bfloat16* __restrict__ A,
                      const __nv_bfloat16* __restrict__ Bm,
                      const float* __restrict__ bias,
                      float* __restrict__ Cm,
                      int K3, long bsB, long bsC) {
    extern __shared__ char smem[];
    uint32_t sb = smem_u32(smem);
    int tid = threadIdx.x, lane = tid & 31, wid = tid >> 5;
    int bx = blockIdx.x, by = blockIdx.y, bz = blockIdx.z;
    int wm = (wid & 1) * 64, wn = (wid >> 1) * 32;

    const __nv_bfloat16* Ab = A + (long)(by * 128) * K3;
    const __nv_bfloat16* Bb = Bm + (long)bz * bsB + (long)(bx * 128) * K3;

    // cp.async mapping: 512 16B-chunks per matrix per stage, 2 per thread
    int r0 = tid >> 1;                 // chunk set 0: rows 0..127, q = 2*(tid&1)
    int q0 = (tid & 1) * 2;
    // second chunk: id = tid + 256 -> row same partition
    int r1 = (tid + 256) >> 1 >= 128 ? ((tid + 256) >> 2) : 0; // unused path guard
    (void)r1;

    uint32_t a_lane = (lane & 15) * (SPITCH * 2) + (lane >> 4) * 16;
    uint32_t b_lane = ((lane & 7) + ((lane >> 4) & 1) * 8) * (SPITCH * 2)
                    + ((lane >> 3) & 1) * 16;

    float acc[4][4][4];
#pragma unroll
    for (int i = 0; i < 4; i++)
#pragma unroll
        for (int j = 0; j < 4; j++)
#pragma unroll
            for (int r = 0; r < 4; r++) acc[i][j][r] = 0.f;

    // stage loader: 4 chunks/thread (2 A + 2 B)
    auto load_stage = [&](int s, int k0) {
        uint32_t sa = sb + s * STAGE_BYTES;
#pragma unroll
        for (int i = 0; i < 2; i++) {
            int id = tid + 256 * i;
            int row = id >> 2, q = id & 3;
            uint32_t so = row * (SPITCH * 2) + q * 16;
            cp16(sa + so, Ab + (long)row * K3 + k0 + q * 8);
            cp16(sa + STG_BYTES + so, Bb + (long)row * K3 + k0 + q * 8);
        }
    };

    int NT = K3 >> 5;
    load_stage(0, 0);  CP_COMMIT();
    load_stage(1, 32); CP_COMMIT();

    for (int t = 0; t < NT; t++) {
        int cur = t - (t / 3) * 3;          // t % 3
        CP_WAIT1();
        __syncthreads();
        if (t + 2 < NT) {
            int nxt = (t + 2) - ((t + 2) / 3) * 3;
            load_stage(nxt, (t + 2) * 32);
        }
        CP_COMMIT();

        uint32_t abase = sb + cur * STAGE_BYTES + a_lane + wm * (SPITCH * 2);
        uint32_t bbase = sb + cur * STAGE_BYTES + STG_BYTES + b_lane + wn * (SPITCH * 2);
#pragma unroll
        for (int ks = 0; ks < 2; ks++) {
            uint32_t a[4][4], b[4][2];
#pragma unroll
            for (int fm = 0; fm < 4; fm++)
                ldsm4(a[fm], abase + fm * 16 * (SPITCH * 2) + ks * 32);
#pragma unroll
            for (int j = 0; j < 2; j++) {
                uint32_t r[4];
                ldsm4(r, bbase + j * 16 * (SPITCH * 2) + ks * 32);
                b[j * 2][0] = r[0]; b[j * 2][1] = r[1];
                b[j * 2 + 1][0] = r[2]; b[j * 2 + 1][1] = r[3];
            }
#pragma unroll
            for (int fm = 0; fm < 4; fm++)
#pragma unroll
                for (int fn = 0; fn < 4; fn++)
                    mma16816(acc[fm][fn], a[fm], b[fn]);
        }
        __syncthreads();
    }

    int rowg = lane >> 2, colg = (lane & 3) * 2;
    float* Cb = Cm + (long)bz * bsC;
#pragma unroll
    for (int fm = 0; fm < 4; fm++) {
        int m0 = by * 128 + wm + fm * 16 + rowg;
        float bv0 = bias[m0], bv1 = bias[m0 + 8];
#pragma unroll
        for (int fn = 0; fn < 4; fn++) {
            int n0 = bx * 128 + wn + fn * 8 + colg;
            float2 v0 = { acc[fm][fn][0] + bv0, acc[fm][fn][1] + bv0 };
            float2 v1 = { acc[fm][fn][2] + bv1, acc[fm][fn][3] + bv1 };
            *reinterpret_cast<float2*>(Cb + (long)m0 * TT + n0) = v0;
            *reinterpret_cast<float2*>(Cb + (long)(m0 + 8) * TT + n0) = v1;
        }
    }
}

// ---------------- launch -----------------------------------------------------
extern "C" void kernel_launch(void* const* d_in, const int* in_sizes, int n_in,
                              void* d_out, int out_size) {
    const float* feature = (const float*)d_in[0];
    const float* frame   = (const float*)d_in[1];
    const float* W1  = (const float*)d_in[2];
    const float* b1  = (const float*)d_in[3];
    const float* g1  = (const float*)d_in[4];
    const float* be1 = (const float*)d_in[5];
    const float* W2  = (const float*)d_in[6];
    const float* b2  = (const float*)d_in[7];
    const float* g2  = (const float*)d_in[8];
    const float* be2 = (const float*)d_in[9];
    const float* W3  = (const float*)d_in[10];
    const float* b3  = (const float*)d_in[11];
    const float* g3  = (const float*)d_in[12];
    const float* be3 = (const float*)d_in[13];

    float* out_mixed = (float*)d_out;
    float* out_feat  = out_mixed + (long)BB * CC * TT;

    __nv_bfloat16 *w12s, *w3s, *bX, *b3buf;
    float *y12, *y3, *bias12;
    cudaGetSymbolAddress((void**)&w12s, g_W12s);
    cudaGetSymbolAddress((void**)&w3s, g_W3s);
    cudaGetSymbolAddress((void**)&bX,  g_bX);
    cudaGetSymbolAddress((void**)&b3buf, g_b3);
    cudaGetSymbolAddress((void**)&y12, g_y12);
    cudaGetSymbolAddress((void**)&y3, g_y3);
    cudaGetSymbolAddress((void**)&bias12, g_bias12);

    cudaFuncSetAttribute(wmma_gemm_kernel,
                         cudaFuncAttributeMaxDynamicSharedMemorySize, 3 * STAGE_BYTES);

    // 0: W2+W1 split + bias concat (one launch)
    prep_kernel<<<3072 + 6, 256>>>(W2, W1, b2, b1);
    // 1: feature transpose-split
    splitx_kernel<<<dim3(TT / 32, CC / 32, BB), dim3(32, 32)>>>(feature);
    // 2: colmean (independent)
    colmean_kernel<<<TFF / 256, 256>>>(frame);
    // 3: stacked GEMM1+2  (profiled slot)
    wmma_gemm_kernel<<<dim3(TT / 128, M12 / 128, BB), 256, 3 * STAGE_BYTES>>>(
        w12s, bX, bias12, y12, K3X, (long)TT * K3X, (long)M12 * TT);

    // W3 split + resample path
    splitw_kernel<<<(CC * 2048) / 256, 256>>>(W3, w3s, CC, 2048);
    cdf_kernel<<<1, 256>>>();
    idx_kernel<<<TT / 256, 256>>>();
    gather_split_kernel<<<dim3(TT / 32, CC / 32, BB), dim3(32, 32)>>>(frame);

    // GroupNorm + ReLU; feat -> fp32 out + bf16 split; fm_short -> bf16 split
    gn_stats_kernel<<<dim3(NGROUPS, BB), 256>>>(y12, (long)M12 * TT, P2 / NGROUPS, 1);
    gn_stats_kernel<<<dim3(NGROUPS, BB), 256>>>(y12 + (long)P2 * TT, (long)M12 * TT,
                                                P1 / NGROUPS, 0);
    gn_split_kernel<<<dim3(TT / 32, P2 / 32, BB), dim3(32, 32)>>>(
        y12, (long)M12 * TT, P2 / NGROUPS, 1, 512, g2, be2, out_feat, (long)P2 * TT);
    gn_split_kernel<<<dim3(TT / 32, P1 / 32, BB), dim3(32, 32)>>>(
        y12 + (long)P2 * TT, (long)M12 * TT, P1 / NGROUPS, 0, 1536, g1, be1,
        (float*)0, 0);

    // GEMM3 over concatenated (split) input, then final GN+ReLU
    wmma_gemm_kernel<<<dim3(TT / 128, CC / 128, BB), 256, 3 * STAGE_BYTES>>>(
        w3s, b3buf, b3, y3, K33, (long)TT * K33, (long)CC * TT);
    gn_stats_kernel<<<dim3(NGROUPS, BB), 256>>>(y3, (long)CC * TT, CC / NGROUPS, 2);
    gn_out_kernel<<<dim3(CC, BB), 256>>>(
        y3, (long)CC * TT, out_mixed, (long)CC * TT, g3, be3, CC / NGROUPS, 2);
}

// round 5
// speedup vs baseline: 1.5173x; 1.0074x over previous
#include <cuda_runtime.h>
#include <cuda_bf16.h>
#include <cstdint>

#define BB 4
#define CC 512
#define TT 2048
#define TFF 4096
#define NGROUPS 32
#define P1 512
#define P2 1024
#define M12 1536
#define K3X 1536   /* 3*512  */
#define K33 6144   /* 3*2048 */

// ---------------- scratch (device globals: allocation-free) ----------------
__device__ double g_colmean[TFF];
__device__ int    g_cdf[TFF];
__device__ int    g_idx[TT];
__device__ __nv_bfloat16 g_W12s[(size_t)M12 * K3X];
__device__ __nv_bfloat16 g_W3s[(size_t)CC * K33];
__device__ float g_bias12[M12];
__device__ __nv_bfloat16 g_bX[(size_t)BB * TT * K3X];   // 25 MB
__device__ __nv_bfloat16 g_b3[(size_t)BB * TT * K33];   // 100 MB
__device__ float g_y12[(size_t)BB * M12 * TT];          // 50 MB
__device__ float g_y3[(size_t)BB * CC * TT];            // 16 MB
__device__ float g_mu[3][BB * NGROUPS];
__device__ float g_rstd[3][BB * NGROUPS];

// ---------------- PTX helpers ----------------------------------------------
__device__ __forceinline__ uint32_t smem_u32(const void* p) {
    uint32_t a;
    asm("{ .reg .u64 t; cvta.to.shared.u64 t, %1; cvt.u32.u64 %0, t; }"
        : "=r"(a) : "l"(p));
    return a;
}
__device__ __forceinline__ void ldsm4(uint32_t* r, uint32_t addr) {
    asm volatile("ldmatrix.sync.aligned.m8n8.x4.shared.b16 {%0,%1,%2,%3}, [%4];"
                 : "=r"(r[0]), "=r"(r[1]), "=r"(r[2]), "=r"(r[3]) : "r"(addr));
}
__device__ __forceinline__ void mma16816(float* c, const uint32_t* a, const uint32_t* b) {
    asm volatile("mma.sync.aligned.m16n8k16.row.col.f32.bf16.bf16.f32 "
                 "{%0,%1,%2,%3}, {%4,%5,%6,%7}, {%8,%9}, {%0,%1,%2,%3};"
                 : "+f"(c[0]), "+f"(c[1]), "+f"(c[2]), "+f"(c[3])
                 : "r"(a[0]), "r"(a[1]), "r"(a[2]), "r"(a[3]),
                   "r"(b[0]), "r"(b[1]));
}
__device__ __forceinline__ void cp16(uint32_t dst, const void* src) {
    asm volatile("cp.async.cg.shared.global [%0], [%1], 16;" :: "r"(dst), "l"(src));
}
#define CP_COMMIT() asm volatile("cp.async.commit_group;")
#define CP_WAIT2()  asm volatile("cp.async.wait_group 2;")

// ---------------- 0) prep: split W2,W1 + concat bias -------------------------
__global__ void prep_kernel(const float* __restrict__ W2, const float* __restrict__ W1,
                            const float* __restrict__ b2, const float* __restrict__ b1) {
    int bid = blockIdx.x;
    if (bid < 2048) {                       // W2: P2 x CC
        int i = bid * 256 + threadIdx.x;
        int m = i / CC, k = i % CC;
        float w = W2[i];
        __nv_bfloat16 hi = __float2bfloat16(w);
        __nv_bfloat16 lo = __float2bfloat16(w - __bfloat162float(hi));
        size_t base = (size_t)m * K3X;
        g_W12s[base + k] = hi; g_W12s[base + CC + k] = hi; g_W12s[base + 2 * CC + k] = lo;
    } else if (bid < 3072) {                // W1: P1 x CC
        int i = (bid - 2048) * 256 + threadIdx.x;
        int m = i / CC, k = i % CC;
        float w = W1[i];
        __nv_bfloat16 hi = __float2bfloat16(w);
        __nv_bfloat16 lo = __float2bfloat16(w - __bfloat162float(hi));
        size_t base = (size_t)(P2 + m) * K3X;
        g_W12s[base + k] = hi; g_W12s[base + CC + k] = hi; g_W12s[base + 2 * CC + k] = lo;
    } else {                                // bias concat
        int i = (bid - 3072) * 256 + threadIdx.x;
        if (i < P2) g_bias12[i] = b2[i];
        else if (i < M12) g_bias12[i] = b1[i - P2];
    }
}

// ---------------- weight split for W3 ----------------------------------------
__global__ void splitw_kernel(const float* __restrict__ W, __nv_bfloat16* __restrict__ A,
                              int M, int K) {
    int i = blockIdx.x * blockDim.x + threadIdx.x;
    if (i >= M * K) return;
    int m = i / K, k = i % K;
    float w = W[i];
    __nv_bfloat16 hi = __float2bfloat16(w);
    __nv_bfloat16 lo = __float2bfloat16(w - __bfloat162float(hi));
    size_t base = (size_t)m * 3 * K;
    A[base + k] = hi; A[base + K + k] = hi; A[base + 2 * K + k] = lo;
}

// ---------------- 1) column means of frame_level_feature[0] ----------------
__global__ void colmean_kernel(const float* __restrict__ frame) {
    int t = blockIdx.x * blockDim.x + threadIdx.x;
    if (t >= TFF) return;
    const float* p = frame + t;
    double s = 0.0;
#pragma unroll 8
    for (int c = 0; c < CC; c++) s += (double)p[(long)c * TFF];
    g_colmean[t] = s * (1.0 / CC);
}

// ---------------- 2) normalize + cumsum + cdf (fp64, one block) ------------
__global__ void cdf_kernel() {
    __shared__ double blocksum[256];
    __shared__ double s_tot;
    int tid = threadIdx.x;
    const int CH = TFF / 256;
    double loc[CH];
    double s = 0.0;
#pragma unroll
    for (int i = 0; i < CH; i++) { s += g_colmean[tid * CH + i]; loc[i] = s; }
    blocksum[tid] = s;
    __syncthreads();
    if (tid == 0) {
        double r = 0.0;
        for (int i = 0; i < 256; i++) { double v = blocksum[i]; blocksum[i] = r; r += v; }
        s_tot = r;
    }
    __syncthreads();
    double base = blocksum[tid];
    double f = (double)TT / s_tot;
#pragma unroll
    for (int i = 0; i < CH; i++) {
        int v = (int)((base + loc[i]) * f);
        if (v > TT - 1) v = TT - 1;
        g_cdf[tid * CH + i] = v;
    }
}

// ---------------- 3) idx = argmin_j |cdf[j] - i| ----------------------------
__global__ void idx_kernel() {
    __shared__ int scdf[TFF];
    for (int j = threadIdx.x; j < TFF; j += blockDim.x) scdf[j] = g_cdf[j];
    __syncthreads();
    int i = blockIdx.x * blockDim.x + threadIdx.x;
    if (i >= TT) return;
    int best = 1 << 30, bj = 0;
    for (int j = 0; j < TFF; j++) {
        int d = scdf[j] - i;
        d = d < 0 ? -d : d;
        if (d < best) { best = d; bj = j; }
    }
    g_idx[i] = bj;
}

// ---------------- 5) feature transpose-split: B' = [hi ; lo ; hi] -----------
__global__ void splitx_kernel(const float* __restrict__ X) {
    __shared__ float tile[32][33];
    int b = blockIdx.z, c0 = blockIdx.y * 32, t0 = blockIdx.x * 32;
    int tx = threadIdx.x, ty = threadIdx.y;
    tile[ty][tx] = X[((long)b * CC + c0 + ty) * TT + t0 + tx];
    __syncthreads();
    float w = tile[tx][ty];
    int n = t0 + ty, k = c0 + tx;
    __nv_bfloat16 hi = __float2bfloat16(w);
    __nv_bfloat16 lo = __float2bfloat16(w - __bfloat162float(hi));
    __nv_bfloat16* d = g_bX + ((size_t)b * TT + n) * K3X;
    d[k] = hi; d[512 + k] = lo; d[1024 + k] = hi;
}

// ---------------- 6) gather + transpose-split into g_b3[.., 0:512] ----------
__global__ void gather_split_kernel(const float* __restrict__ frame) {
    __shared__ float tile[32][33];
    int b = blockIdx.z, c0 = blockIdx.y * 32, t0 = blockIdx.x * 32;
    int tx = threadIdx.x, ty = threadIdx.y;
    tile[ty][tx] = frame[((long)b * CC + c0 + ty) * TFF + g_idx[t0 + tx]];
    __syncthreads();
    float w = tile[tx][ty];
    int n = t0 + ty, k = c0 + tx;
    __nv_bfloat16 hi = __float2bfloat16(w);
    __nv_bfloat16 lo = __float2bfloat16(w - __bfloat162float(hi));
    __nv_bfloat16* d = g_b3 + ((size_t)b * TT + n) * K33;
    d[k] = hi; d[2048 + k] = lo; d[4096 + k] = hi;
}

// ---------------- 7) GroupNorm stats ----------------------------------------
__global__ void gn_stats_kernel(const float* __restrict__ buf, long bstride,
                                int chpg, int stage) {
    int g = blockIdx.x, b = blockIdx.y;
    long L = (long)chpg * TT;
    const float* p = buf + (long)b * bstride + (long)g * L;
    double s = 0.0, s2 = 0.0;
    for (long i = (long)threadIdx.x * 4; i < L; i += (long)blockDim.x * 4) {
        float4 v = *reinterpret_cast<const float4*>(p + i);
        s  += (double)v.x + (double)v.y + (double)v.z + (double)v.w;
        s2 += (double)v.x * v.x + (double)v.y * v.y + (double)v.z * v.z + (double)v.w * v.w;
    }
    __shared__ double sh[256], sh2[256];
    sh[threadIdx.x] = s; sh2[threadIdx.x] = s2;
    __syncthreads();
    for (int off = 128; off > 0; off >>= 1) {
        if (threadIdx.x < off) {
            sh[threadIdx.x]  += sh[threadIdx.x + off];
            sh2[threadIdx.x] += sh2[threadIdx.x + off];
        }
        __syncthreads();
    }
    if (threadIdx.x == 0) {
        double mean = sh[0] / (double)L;
        double var  = sh2[0] / (double)L - mean * mean;
        g_mu[stage][b * NGROUPS + g]   = (float)mean;
        g_rstd[stage][b * NGROUPS + g] = (float)rsqrt(var + 1e-5);
    }
}

// ------- 8) GN+ReLU, write optional fp32 out AND transposed bf16 split ------
__global__ void gn_split_kernel(const float* __restrict__ y, long ybs,
                                int chpg, int stage, int chanoff,
                                const float* __restrict__ gamma,
                                const float* __restrict__ beta,
                                float* __restrict__ outf, long obs) {
    __shared__ float tile[32][33];
    int b = blockIdx.z, c0 = blockIdx.y * 32, t0 = blockIdx.x * 32;
    int tx = threadIdx.x, ty = threadIdx.y;
    int c = c0 + ty;
    float mu = g_mu[stage][b * NGROUPS + c / chpg];
    float rs = g_rstd[stage][b * NGROUPS + c / chpg];
    float ga = gamma[c] * rs, bt = beta[c] - mu * ga;
    float v = fmaxf(fmaf(y[(long)b * ybs + (long)c * TT + t0 + tx], ga, bt), 0.f);
    if (outf) outf[(long)b * obs + (long)c * TT + t0 + tx] = v;
    tile[ty][tx] = v;
    __syncthreads();
    float w = tile[tx][ty];
    int n = t0 + ty, k = chanoff + c0 + tx;
    __nv_bfloat16 hi = __float2bfloat16(w);
    __nv_bfloat16 lo = __float2bfloat16(w - __bfloat162float(hi));
    __nv_bfloat16* d = g_b3 + ((size_t)b * TT + n) * K33;
    d[k] = hi; d[2048 + k] = lo; d[4096 + k] = hi;
}

// ---------------- 9) final GN+ReLU (fp32 out only) ---------------------------
__global__ void gn_out_kernel(const float* __restrict__ in, long in_bs,
                              float* __restrict__ out, long out_bs,
                              const float* __restrict__ gamma,
                              const float* __restrict__ beta,
                              int chpg, int stage) {
    int c = blockIdx.x, b = blockIdx.y;
    int g = c / chpg;
    float mu = g_mu[stage][b * NGROUPS + g];
    float rs = g_rstd[stage][b * NGROUPS + g];
    float ga = gamma[c] * rs, bt = beta[c] - mu * ga;
    const float* ip = in + (long)b * in_bs + (long)c * TT;
    float* op = out + (long)b * out_bs + (long)c * TT;
    for (int i = threadIdx.x * 4; i < TT; i += blockDim.x * 4) {
        float4 v = *reinterpret_cast<const float4*>(ip + i);
        v.x = fmaxf(fmaf(v.x, ga, bt), 0.f);
        v.y = fmaxf(fmaf(v.y, ga, bt), 0.f);
        v.z = fmaxf(fmaf(v.z, ga, bt), 0.f);
        v.w = fmaxf(fmaf(v.w, ga, bt), 0.f);
        *reinterpret_cast<float4*>(op + i) = v;
    }
}

// ---------------- 10) HMMA bf16 GEMM, cp.async 4-stage single-sync ----------
// A' [M, K3] row-major, B' [B][N=2048, K3] row-major (both K-contiguous).
// C [B][M, 2048] fp32. Block tile 128x128, BK=32, 8 warps of 64x32.
#define SPITCH 40                 /* bf16 elems per smem row (80 B) */
#define STG_BYTES (128 * SPITCH * 2)      /* 10240 per matrix */
#define STAGE_BYTES (2 * STG_BYTES)       /* 20480 per stage */
#define NSTAGE 4

__global__ __launch_bounds__(256, 2)
void wmma_gemm_kernel(const __nv_bfloat16* __restrict__ A,
                      const __nv_bfloat16* __restrict__ Bm,
                      const float* __restrict__ bias,
                      float* __restrict__ Cm,
                      int K3, long bsB, long bsC) {
    extern __shared__ char smem[];
    uint32_t sb = smem_u32(smem);
    int tid = threadIdx.x, lane = tid & 31, wid = tid >> 5;
    int bx = blockIdx.x, by = blockIdx.y, bz = blockIdx.z;
    int wm = (wid & 1) * 64, wn = (wid >> 1) * 32;

    const __nv_bfloat16* Ab = A + (long)(by * 128) * K3;
    const __nv_bfloat16* Bb = Bm + (long)bz * bsB + (long)(bx * 128) * K3;

    uint32_t a_lane = (lane & 15) * (SPITCH * 2) + (lane >> 4) * 16;
    uint32_t b_lane = ((lane & 7) + ((lane >> 4) & 1) * 8) * (SPITCH * 2)
                    + ((lane >> 3) & 1) * 16;

    float acc[4][4][4];
#pragma unroll
    for (int i = 0; i < 4; i++)
#pragma unroll
        for (int j = 0; j < 4; j++)
#pragma unroll
            for (int r = 0; r < 4; r++) acc[i][j][r] = 0.f;

    // stage loader: 4 chunks/thread (2 A + 2 B)
    auto load_stage = [&](int s, int k0) {
        uint32_t sa = sb + s * STAGE_BYTES;
#pragma unroll
        for (int i = 0; i < 2; i++) {
            int id = tid + 256 * i;
            int row = id >> 2, q = id & 3;
            uint32_t so = row * (SPITCH * 2) + q * 16;
            cp16(sa + so, Ab + (long)row * K3 + k0 + q * 8);
            cp16(sa + STG_BYTES + so, Bb + (long)row * K3 + k0 + q * 8);
        }
    };

    int NT = K3 >> 5;
    load_stage(0, 0);  CP_COMMIT();
    load_stage(1, 32); CP_COMMIT();
    load_stage(2, 64); CP_COMMIT();

    for (int t = 0; t < NT; t++) {
        int cur = t & 3;
        CP_WAIT2();                 // stage t complete (<=2 younger pending)
        __syncthreads();            // all warps done with slot (t-1)&3
        if (t + 3 < NT) load_stage((t + 3) & 3, (t + 3) * 32);
        CP_COMMIT();                // commit (possibly empty) keeps count exact

        uint32_t abase = sb + cur * STAGE_BYTES + a_lane + wm * (SPITCH * 2);
        uint32_t bbase = sb + cur * STAGE_BYTES + STG_BYTES + b_lane + wn * (SPITCH * 2);
#pragma unroll
        for (int ks = 0; ks < 2; ks++) {
            uint32_t a[4][4], b[4][2];
#pragma unroll
            for (int fm = 0; fm < 4; fm++)
                ldsm4(a[fm], abase + fm * 16 * (SPITCH * 2) + ks * 32);
#pragma unroll
            for (int j = 0; j < 2; j++) {
                uint32_t r[4];
                ldsm4(r, bbase + j * 16 * (SPITCH * 2) + ks * 32);
                b[j * 2][0] = r[0]; b[j * 2][1] = r[1];
                b[j * 2 + 1][0] = r[2]; b[j * 2 + 1][1] = r[3];
            }
#pragma unroll
            for (int fm = 0; fm < 4; fm++)
#pragma unroll
                for (int fn = 0; fn < 4; fn++)
                    mma16816(acc[fm][fn], a[fm], b[fn]);
        }
    }

    int rowg = lane >> 2, colg = (lane & 3) * 2;
    float* Cb = Cm + (long)bz * bsC;
#pragma unroll
    for (int fm = 0; fm < 4; fm++) {
        int m0 = by * 128 + wm + fm * 16 + rowg;
        float bv0 = bias[m0], bv1 = bias[m0 + 8];
#pragma unroll
        for (int fn = 0; fn < 4; fn++) {
            int n0 = bx * 128 + wn + fn * 8 + colg;
            float2 v0 = { acc[fm][fn][0] + bv0, acc[fm][fn][1] + bv0 };
            float2 v1 = { acc[fm][fn][2] + bv1, acc[fm][fn][3] + bv1 };
            *reinterpret_cast<float2*>(Cb + (long)m0 * TT + n0) = v0;
            *reinterpret_cast<float2*>(Cb + (long)(m0 + 8) * TT + n0) = v1;
        }
    }
}

// ---------------- launch -----------------------------------------------------
extern "C" void kernel_launch(void* const* d_in, const int* in_sizes, int n_in,
                              void* d_out, int out_size) {
    const float* feature = (const float*)d_in[0];
    const float* frame   = (const float*)d_in[1];
    const float* W1  = (const float*)d_in[2];
    const float* b1  = (const float*)d_in[3];
    const float* g1  = (const float*)d_in[4];
    const float* be1 = (const float*)d_in[5];
    const float* W2  = (const float*)d_in[6];
    const float* b2  = (const float*)d_in[7];
    const float* g2  = (const float*)d_in[8];
    const float* be2 = (const float*)d_in[9];
    const float* W3  = (const float*)d_in[10];
    const float* b3  = (const float*)d_in[11];
    const float* g3  = (const float*)d_in[12];
    const float* be3 = (const float*)d_in[13];

    float* out_mixed = (float*)d_out;
    float* out_feat  = out_mixed + (long)BB * CC * TT;

    __nv_bfloat16 *w12s, *w3s, *bX, *b3buf;
    float *y12, *y3, *bias12;
    cudaGetSymbolAddress((void**)&w12s, g_W12s);
    cudaGetSymbolAddress((void**)&w3s, g_W3s);
    cudaGetSymbolAddress((void**)&bX,  g_bX);
    cudaGetSymbolAddress((void**)&b3buf, g_b3);
    cudaGetSymbolAddress((void**)&y12, g_y12);
    cudaGetSymbolAddress((void**)&y3, g_y3);
    cudaGetSymbolAddress((void**)&bias12, g_bias12);

    cudaFuncSetAttribute(wmma_gemm_kernel,
                         cudaFuncAttributeMaxDynamicSharedMemorySize,
                         NSTAGE * STAGE_BYTES);

    // 0: W2+W1 split + bias concat (one launch)
    prep_kernel<<<3072 + 6, 256>>>(W2, W1, b2, b1);
    // 1: feature transpose-split
    splitx_kernel<<<dim3(TT / 32, CC / 32, BB), dim3(32, 32)>>>(feature);
    // 2: colmean (independent)
    colmean_kernel<<<TFF / 256, 256>>>(frame);
    // 3: stacked GEMM1+2  (profiled slot)
    wmma_gemm_kernel<<<dim3(TT / 128, M12 / 128, BB), 256, NSTAGE * STAGE_BYTES>>>(
        w12s, bX, bias12, y12, K3X, (long)TT * K3X, (long)M12 * TT);

    // W3 split + resample path
    splitw_kernel<<<(CC * 2048) / 256, 256>>>(W3, w3s, CC, 2048);
    cdf_kernel<<<1, 256>>>();
    idx_kernel<<<TT / 256, 256>>>();
    gather_split_kernel<<<dim3(TT / 32, CC / 32, BB), dim3(32, 32)>>>(frame);

    // GroupNorm + ReLU; feat -> fp32 out + bf16 split; fm_short -> bf16 split
    gn_stats_kernel<<<dim3(NGROUPS, BB), 256>>>(y12, (long)M12 * TT, P2 / NGROUPS, 1);
    gn_stats_kernel<<<dim3(NGROUPS, BB), 256>>>(y12 + (long)P2 * TT, (long)M12 * TT,
                                                P1 / NGROUPS, 0);
    gn_split_kernel<<<dim3(TT / 32, P2 / 32, BB), dim3(32, 32)>>>(
        y12, (long)M12 * TT, P2 / NGROUPS, 1, 512, g2, be2, out_feat, (long)P2 * TT);
    gn_split_kernel<<<dim3(TT / 32, P1 / 32, BB), dim3(32, 32)>>>(
        y12 + (long)P2 * TT, (long)M12 * TT, P1 / NGROUPS, 0, 1536, g1, be1,
        (float*)0, 0);

    // GEMM3 over concatenated (split) input, then final GN+ReLU
    wmma_gemm_kernel<<<dim3(TT / 128, CC / 128, BB), 256, NSTAGE * STAGE_BYTES>>>(
        w3s, b3buf, b3, y3, K33, (long)TT * K33, (long)CC * TT);
    gn_stats_kernel<<<dim3(NGROUPS, BB), 256>>>(y3, (long)CC * TT, CC / NGROUPS, 2);
    gn_out_kernel<<<dim3(CC, BB), 256>>>(
        y3, (long)CC * TT, out_mixed, (long)CC * TT, g3, be3, CC / NGROUPS, 2);
}

// round 6
// speedup vs baseline: 1.7672x; 1.1647x over previous
#include <cuda_runtime.h>
#include <cuda_fp16.h>
#include <cstdint>

#define BB 4
#define CC 512
#define TT 2048
#define TFF 4096
#define NGROUPS 32
#define P1 512
#define P2 1024
#define M12 1536
#define K2X 1024   /* 2*512  */
#define K23 4096   /* 2*2048 */

// ---------------- scratch (device globals: allocation-free) ----------------
__device__ double g_colmean[TFF];
__device__ int    g_cdf[TFF];
__device__ int    g_idx[TT];
__device__ __half g_W12s[(size_t)M12 * K2X];
__device__ __half g_W3s[(size_t)CC * K23];
__device__ float g_bias12[M12];
__device__ __half g_bX[(size_t)BB * TT * K2X];   // 17 MB
__device__ __half g_b3[(size_t)BB * TT * K23];   // 67 MB
__device__ float g_y12[(size_t)BB * M12 * TT];   // 50 MB
__device__ float g_y3[(size_t)BB * CC * TT];     // 16 MB
__device__ float g_mu[3][BB * NGROUPS];
__device__ float g_rstd[3][BB * NGROUPS];

// ---------------- PTX helpers ----------------------------------------------
__device__ __forceinline__ uint32_t smem_u32(const void* p) {
    uint32_t a;
    asm("{ .reg .u64 t; cvta.to.shared.u64 t, %1; cvt.u32.u64 %0, t; }"
        : "=r"(a) : "l"(p));
    return a;
}
__device__ __forceinline__ void ldsm4(uint32_t* r, uint32_t addr) {
    asm volatile("ldmatrix.sync.aligned.m8n8.x4.shared.b16 {%0,%1,%2,%3}, [%4];"
                 : "=r"(r[0]), "=r"(r[1]), "=r"(r[2]), "=r"(r[3]) : "r"(addr));
}
__device__ __forceinline__ void mma16816(float* c, const uint32_t* a, const uint32_t* b) {
    asm volatile("mma.sync.aligned.m16n8k16.row.col.f32.f16.f16.f32 "
                 "{%0,%1,%2,%3}, {%4,%5,%6,%7}, {%8,%9}, {%0,%1,%2,%3};"
                 : "+f"(c[0]), "+f"(c[1]), "+f"(c[2]), "+f"(c[3])
                 : "r"(a[0]), "r"(a[1]), "r"(a[2]), "r"(a[3]),
                   "r"(b[0]), "r"(b[1]));
}
__device__ __forceinline__ void cp16(uint32_t dst, const void* src) {
    asm volatile("cp.async.cg.shared.global [%0], [%1], 16;" :: "r"(dst), "l"(src));
}
#define CP_COMMIT() asm volatile("cp.async.commit_group;")
#define CP_WAIT2()  asm volatile("cp.async.wait_group 2;")

__device__ __forceinline__ void split2(float w, __half& hi, __half& lo) {
    hi = __float2half_rn(w);
    lo = __float2half_rn(w - __half2float(hi));
}

// ---------------- 0) prep: W2,W1 -> fp16 hi duplicated + bias concat --------
__global__ void prep_kernel(const float* __restrict__ W2, const float* __restrict__ W1,
                            const float* __restrict__ b2, const float* __restrict__ b1) {
    int bid = blockIdx.x;
    if (bid < 2048) {                       // W2: P2 x CC
        int i = bid * 256 + threadIdx.x;
        int m = i / CC, k = i % CC;
        __half hi = __float2half_rn(W2[i]);
        size_t base = (size_t)m * K2X;
        g_W12s[base + k] = hi; g_W12s[base + CC + k] = hi;
    } else if (bid < 3072) {                // W1: P1 x CC
        int i = (bid - 2048) * 256 + threadIdx.x;
        int m = i / CC, k = i % CC;
        __half hi = __float2half_rn(W1[i]);
        size_t base = (size_t)(P2 + m) * K2X;
        g_W12s[base + k] = hi; g_W12s[base + CC + k] = hi;
    } else {                                // bias concat
        int i = (bid - 3072) * 256 + threadIdx.x;
        if (i < P2) g_bias12[i] = b2[i];
        else if (i < M12) g_bias12[i] = b1[i - P2];
    }
}

// ---------------- W3 -> fp16 hi duplicated ----------------------------------
__global__ void splitw3_kernel(const float* __restrict__ W) {
    int i = blockIdx.x * blockDim.x + threadIdx.x;
    int m = i / 2048, k = i % 2048;
    __half hi = __float2half_rn(W[i]);
    size_t base = (size_t)m * K23;
    g_W3s[base + k] = hi; g_W3s[base + 2048 + k] = hi;
}

// ---------------- 1) column means of frame_level_feature[0] ----------------
__global__ void colmean_kernel(const float* __restrict__ frame) {
    int t = blockIdx.x * blockDim.x + threadIdx.x;
    if (t >= TFF) return;
    const float* p = frame + t;
    double s = 0.0;
#pragma unroll 8
    for (int c = 0; c < CC; c++) s += (double)p[(long)c * TFF];
    g_colmean[t] = s * (1.0 / CC);
}

// ---------------- 2) normalize + cumsum + cdf (fp64, one block) ------------
__global__ void cdf_kernel() {
    __shared__ double blocksum[256];
    __shared__ double s_tot;
    int tid = threadIdx.x;
    const int CH = TFF / 256;
    double loc[CH];
    double s = 0.0;
#pragma unroll
    for (int i = 0; i < CH; i++) { s += g_colmean[tid * CH + i]; loc[i] = s; }
    blocksum[tid] = s;
    __syncthreads();
    if (tid == 0) {
        double r = 0.0;
        for (int i = 0; i < 256; i++) { double v = blocksum[i]; blocksum[i] = r; r += v; }
        s_tot = r;
    }
    __syncthreads();
    double base = blocksum[tid];
    double f = (double)TT / s_tot;
#pragma unroll
    for (int i = 0; i < CH; i++) {
        int v = (int)((base + loc[i]) * f);
        if (v > TT - 1) v = TT - 1;
        g_cdf[tid * CH + i] = v;
    }
}

// ---------------- 3) idx = argmin_j |cdf[j] - i| ----------------------------
__global__ void idx_kernel() {
    __shared__ int scdf[TFF];
    for (int j = threadIdx.x; j < TFF; j += blockDim.x) scdf[j] = g_cdf[j];
    __syncthreads();
    int i = blockIdx.x * blockDim.x + threadIdx.x;
    if (i >= TT) return;
    int best = 1 << 30, bj = 0;
    for (int j = 0; j < TFF; j++) {
        int d = scdf[j] - i;
        d = d < 0 ? -d : d;
        if (d < best) { best = d; bj = j; }
    }
    g_idx[i] = bj;
}

// ---------------- 5) feature transpose-split: B' = [hi ; lo] ----------------
__global__ void splitx_kernel(const float* __restrict__ X) {
    __shared__ float tile[32][33];
    int b = blockIdx.z, c0 = blockIdx.y * 32, t0 = blockIdx.x * 32;
    int tx = threadIdx.x, ty = threadIdx.y;
    tile[ty][tx] = X[((long)b * CC + c0 + ty) * TT + t0 + tx];
    __syncthreads();
    float w = tile[tx][ty];
    int n = t0 + ty, k = c0 + tx;
    __half hi, lo; split2(w, hi, lo);
    __half* d = g_bX + ((size_t)b * TT + n) * K2X;
    d[k] = hi; d[512 + k] = lo;
}

// ---------------- 6) gather + transpose-split into g_b3 ---------------------
__global__ void gather_split_kernel(const float* __restrict__ frame) {
    __shared__ float tile[32][33];
    int b = blockIdx.z, c0 = blockIdx.y * 32, t0 = blockIdx.x * 32;
    int tx = threadIdx.x, ty = threadIdx.y;
    tile[ty][tx] = frame[((long)b * CC + c0 + ty) * TFF + g_idx[t0 + tx]];
    __syncthreads();
    float w = tile[tx][ty];
    int n = t0 + ty, k = c0 + tx;
    __half hi, lo; split2(w, hi, lo);
    __half* d = g_b3 + ((size_t)b * TT + n) * K23;
    d[k] = hi; d[2048 + k] = lo;
}

// ---------------- 7) GroupNorm stats ----------------------------------------
__global__ void gn_stats_kernel(const float* __restrict__ buf, long bstride,
                                int chpg, int stage) {
    int g = blockIdx.x, b = blockIdx.y;
    long L = (long)chpg * TT;
    const float* p = buf + (long)b * bstride + (long)g * L;
    double s = 0.0, s2 = 0.0;
    for (long i = (long)threadIdx.x * 4; i < L; i += (long)blockDim.x * 4) {
        float4 v = *reinterpret_cast<const float4*>(p + i);
        s  += (double)v.x + (double)v.y + (double)v.z + (double)v.w;
        s2 += (double)v.x * v.x + (double)v.y * v.y + (double)v.z * v.z + (double)v.w * v.w;
    }
    __shared__ double sh[256], sh2[256];
    sh[threadIdx.x] = s; sh2[threadIdx.x] = s2;
    __syncthreads();
    for (int off = 128; off > 0; off >>= 1) {
        if (threadIdx.x < off) {
            sh[threadIdx.x]  += sh[threadIdx.x + off];
            sh2[threadIdx.x] += sh2[threadIdx.x + off];
        }
        __syncthreads();
    }
    if (threadIdx.x == 0) {
        double mean = sh[0] / (double)L;
        double var  = sh2[0] / (double)L - mean * mean;
        g_mu[stage][b * NGROUPS + g]   = (float)mean;
        g_rstd[stage][b * NGROUPS + g] = (float)rsqrt(var + 1e-5);
    }
}

// ------- 8) GN+ReLU, write optional fp32 out AND transposed fp16 split ------
__global__ void gn_split_kernel(const float* __restrict__ y, long ybs,
                                int chpg, int stage, int chanoff,
                                const float* __restrict__ gamma,
                                const float* __restrict__ beta,
                                float* __restrict__ outf, long obs) {
    __shared__ float tile[32][33];
    int b = blockIdx.z, c0 = blockIdx.y * 32, t0 = blockIdx.x * 32;
    int tx = threadIdx.x, ty = threadIdx.y;
    int c = c0 + ty;
    float mu = g_mu[stage][b * NGROUPS + c / chpg];
    float rs = g_rstd[stage][b * NGROUPS + c / chpg];
    float ga = gamma[c] * rs, bt = beta[c] - mu * ga;
    float v = fmaxf(fmaf(y[(long)b * ybs + (long)c * TT + t0 + tx], ga, bt), 0.f);
    if (outf) outf[(long)b * obs + (long)c * TT + t0 + tx] = v;
    tile[ty][tx] = v;
    __syncthreads();
    float w = tile[tx][ty];
    int n = t0 + ty, k = chanoff + c0 + tx;
    __half hi, lo; split2(w, hi, lo);
    __half* d = g_b3 + ((size_t)b * TT + n) * K23;
    d[k] = hi; d[2048 + k] = lo;
}

// ---------------- 9) final GN+ReLU (fp32 out only) ---------------------------
__global__ void gn_out_kernel(const float* __restrict__ in, long in_bs,
                              float* __restrict__ out, long out_bs,
                              const float* __restrict__ gamma,
                              const float* __restrict__ beta,
                              int chpg, int stage) {
    int c = blockIdx.x, b = blockIdx.y;
    int g = c / chpg;
    float mu = g_mu[stage][b * NGROUPS + g];
    float rs = g_rstd[stage][b * NGROUPS + g];
    float ga = gamma[c] * rs, bt = beta[c] - mu * ga;
    const float* ip = in + (long)b * in_bs + (long)c * TT;
    float* op = out + (long)b * out_bs + (long)c * TT;
    for (int i = threadIdx.x * 4; i < TT; i += blockDim.x * 4) {
        float4 v = *reinterpret_cast<const float4*>(ip + i);
        v.x = fmaxf(fmaf(v.x, ga, bt), 0.f);
        v.y = fmaxf(fmaf(v.y, ga, bt), 0.f);
        v.z = fmaxf(fmaf(v.z, ga, bt), 0.f);
        v.w = fmaxf(fmaf(v.w, ga, bt), 0.f);
        *reinterpret_cast<float4*>(op + i) = v;
    }
}

// ---------------- 10) HMMA fp16 GEMM, cp.async 4-stage single-sync ----------
// A' [M, K2] row-major, B' [B][N=2048, K2] row-major (both K-contiguous).
// C [B][M, 2048] fp32. Block tile 128x128, BK=32, 8 warps of 64x32.
#define SPITCH 40                 /* fp16 elems per smem row (80 B) */
#define STG_BYTES (128 * SPITCH * 2)      /* 10240 per matrix */
#define STAGE_BYTES (2 * STG_BYTES)       /* 20480 per stage */
#define NSTAGE 4

__global__ __launch_bounds__(256, 2)
void wmma_gemm_kernel(const __half* __restrict__ A,
                      const __half* __restrict__ Bm,
                      const float* __restrict__ bias,
                      float* __restrict__ Cm,
                      int K2, long bsB, long bsC) {
    extern __shared__ char smem[];
    uint32_t sb = smem_u32(smem);
    int tid = threadIdx.x, lane = tid & 31, wid = tid >> 5;
    int bx = blockIdx.x, by = blockIdx.y, bz = blockIdx.z;
    int wm = (wid & 1) * 64, wn = (wid >> 1) * 32;

    const __half* Ab = A + (long)(by * 128) * K2;
    const __half* Bb = Bm + (long)bz * bsB + (long)(bx * 128) * K2;

    uint32_t a_lane = (lane & 15) * (SPITCH * 2) + (lane >> 4) * 16;
    uint32_t b_lane = ((lane & 7) + ((lane >> 4) & 1) * 8) * (SPITCH * 2)
                    + ((lane >> 3) & 1) * 16;

    float acc[4][4][4];
#pragma unroll
    for (int i = 0; i < 4; i++)
#pragma unroll
        for (int j = 0; j < 4; j++)
#pragma unroll
            for (int r = 0; r < 4; r++) acc[i][j][r] = 0.f;

    auto load_stage = [&](int s, int k0) {
        uint32_t sa = sb + s * STAGE_BYTES;
#pragma unroll
        for (int i = 0; i < 2; i++) {
            int id = tid + 256 * i;
            int row = id >> 2, q = id & 3;
            uint32_t so = row * (SPITCH * 2) + q * 16;
            cp16(sa + so, Ab + (long)row * K2 + k0 + q * 8);
            cp16(sa + STG_BYTES + so, Bb + (long)row * K2 + k0 + q * 8);
        }
    };

    int NT = K2 >> 5;
    load_stage(0, 0);  CP_COMMIT();
    load_stage(1, 32); CP_COMMIT();
    load_stage(2, 64); CP_COMMIT();

    for (int t = 0; t < NT; t++) {
        int cur = t & 3;
        CP_WAIT2();
        __syncthreads();
        if (t + 3 < NT) load_stage((t + 3) & 3, (t + 3) * 32);
        CP_COMMIT();

        uint32_t abase = sb + cur * STAGE_BYTES + a_lane + wm * (SPITCH * 2);
        uint32_t bbase = sb + cur * STAGE_BYTES + STG_BYTES + b_lane + wn * (SPITCH * 2);
#pragma unroll
        for (int ks = 0; ks < 2; ks++) {
            uint32_t a[4][4], b[4][2];
#pragma unroll
            for (int fm = 0; fm < 4; fm++)
                ldsm4(a[fm], abase + fm * 16 * (SPITCH * 2) + ks * 32);
#pragma unroll
            for (int j = 0; j < 2; j++) {
                uint32_t r[4];
                ldsm4(r, bbase + j * 16 * (SPITCH * 2) + ks * 32);
                b[j * 2][0] = r[0]; b[j * 2][1] = r[1];
                b[j * 2 + 1][0] = r[2]; b[j * 2 + 1][1] = r[3];
            }
#pragma unroll
            for (int fm = 0; fm < 4; fm++)
#pragma unroll
                for (int fn = 0; fn < 4; fn++)
                    mma16816(acc[fm][fn], a[fm], b[fn]);
        }
    }

    int rowg = lane >> 2, colg = (lane & 3) * 2;
    float* Cb = Cm + (long)bz * bsC;
#pragma unroll
    for (int fm = 0; fm < 4; fm++) {
        int m0 = by * 128 + wm + fm * 16 + rowg;
        float bv0 = bias[m0], bv1 = bias[m0 + 8];
#pragma unroll
        for (int fn = 0; fn < 4; fn++) {
            int n0 = bx * 128 + wn + fn * 8 + colg;
            float2 v0 = { acc[fm][fn][0] + bv0, acc[fm][fn][1] + bv0 };
            float2 v1 = { acc[fm][fn][2] + bv1, acc[fm][fn][3] + bv1 };
            *reinterpret_cast<float2*>(Cb + (long)m0 * TT + n0) = v0;
            *reinterpret_cast<float2*>(Cb + (long)(m0 + 8) * TT + n0) = v1;
        }
    }
}

// ---------------- launch -----------------------------------------------------
extern "C" void kernel_launch(void* const* d_in, const int* in_sizes, int n_in,
                              void* d_out, int out_size) {
    const float* feature = (const float*)d_in[0];
    const float* frame   = (const float*)d_in[1];
    const float* W1  = (const float*)d_in[2];
    const float* b1  = (const float*)d_in[3];
    const float* g1  = (const float*)d_in[4];
    const float* be1 = (const float*)d_in[5];
    const float* W2  = (const float*)d_in[6];
    const float* b2  = (const float*)d_in[7];
    const float* g2  = (const float*)d_in[8];
    const float* be2 = (const float*)d_in[9];
    const float* W3  = (const float*)d_in[10];
    const float* b3  = (const float*)d_in[11];
    const float* g3  = (const float*)d_in[12];
    const float* be3 = (const float*)d_in[13];

    float* out_mixed = (float*)d_out;
    float* out_feat  = out_mixed + (long)BB * CC * TT;

    __half *w12s, *w3s, *bX, *b3buf;
    float *y12, *y3, *bias12;
    cudaGetSymbolAddress((void**)&w12s, g_W12s);
    cudaGetSymbolAddress((void**)&w3s, g_W3s);
    cudaGetSymbolAddress((void**)&bX,  g_bX);
    cudaGetSymbolAddress((void**)&b3buf, g_b3);
    cudaGetSymbolAddress((void**)&y12, g_y12);
    cudaGetSymbolAddress((void**)&y3, g_y3);
    cudaGetSymbolAddress((void**)&bias12, g_bias12);

    cudaFuncSetAttribute(wmma_gemm_kernel,
                         cudaFuncAttributeMaxDynamicSharedMemorySize,
                         NSTAGE * STAGE_BYTES);

    // 0: W2+W1 fp16 + bias concat
    prep_kernel<<<3072 + 6, 256>>>(W2, W1, b2, b1);
    // 1: feature transpose-split
    splitx_kernel<<<dim3(TT / 32, CC / 32, BB), dim3(32, 32)>>>(feature);
    // 2: colmean (independent)
    colmean_kernel<<<TFF / 256, 256>>>(frame);
    // 3: stacked GEMM1+2  (profiled slot)
    wmma_gemm_kernel<<<dim3(TT / 128, M12 / 128, BB), 256, NSTAGE * STAGE_BYTES>>>(
        w12s, bX, bias12, y12, K2X, (long)TT * K2X, (long)M12 * TT);

    // W3 fp16 + resample path
    splitw3_kernel<<<(CC * 2048) / 256, 256>>>(W3);
    cdf_kernel<<<1, 256>>>();
    idx_kernel<<<TT / 256, 256>>>();
    gather_split_kernel<<<dim3(TT / 32, CC / 32, BB), dim3(32, 32)>>>(frame);

    // GroupNorm + ReLU; feat -> fp32 out + fp16 split; fm_short -> fp16 split
    gn_stats_kernel<<<dim3(NGROUPS, BB), 256>>>(y12, (long)M12 * TT, P2 / NGROUPS, 1);
    gn_stats_kernel<<<dim3(NGROUPS, BB), 256>>>(y12 + (long)P2 * TT, (long)M12 * TT,
                                                P1 / NGROUPS, 0);
    gn_split_kernel<<<dim3(TT / 32, P2 / 32, BB), dim3(32, 32)>>>(
        y12, (long)M12 * TT, P2 / NGROUPS, 1, 512, g2, be2, out_feat, (long)P2 * TT);
    gn_split_kernel<<<dim3(TT / 32, P1 / 32, BB), dim3(32, 32)>>>(
        y12 + (long)P2 * TT, (long)M12 * TT, P1 / NGROUPS, 0, 1536, g1, be1,
        (float*)0, 0);

    // GEMM3 over concatenated (split) input, then final GN+ReLU
    wmma_gemm_kernel<<<dim3(TT / 128, CC / 128, BB), 256, NSTAGE * STAGE_BYTES>>>(
        w3s, b3buf, b3, y3, K23, (long)TT * K23, (long)CC * TT);
    gn_stats_kernel<<<dim3(NGROUPS, BB), 256>>>(y3, (long)CC * TT, CC / NGROUPS, 2);
    gn_out_kernel<<<dim3(CC, BB), 256>>>(
        y3, (long)CC * TT, out_mixed, (long)CC * TT, g3, be3, CC / NGROUPS, 2);
}